// round 1
// baseline (speedup 1.0000x reference)
#include <cuda_runtime.h>
#include <math.h>

#define HW 65536
#define CIN 256
#define CMID 64

// ---- scratch (device globals; allocation is forbidden) ----
__device__ float g_y[4 * CMID * HW];      // after input conv1x1  (64 MiB)
__device__ float g_edge[4 * CMID * HW];   // raw edge map         (64 MiB)
__device__ float g_sums[4 * CMID];        // per-(b,c) raw-edge sums
__device__ unsigned int g_maxbits;        // global max (float bits, all vals >= 0)
__device__ float g_weff[4 * CMID * CMID]; // folded output weights per batch

// ---------------------------------------------------------------------------
__global__ void k_init() {
    int t = threadIdx.x;
    if (t < 256) g_sums[t] = 0.f;
    if (t == 0) g_maxbits = 0u;
}

// ---------------------------------------------------------------------------
// conv1x1 in: y[b,o,p] = b_in[o] + sum_c w_in[o,c] * x[b,c,p]
// 1 thread per pixel, 64 accumulators, weights staged in smem in 2 halves.
__global__ void __launch_bounds__(256) k_conv_in(const float* __restrict__ x,
                                                 const float* __restrict__ w,
                                                 const float* __restrict__ bias) {
    __shared__ float ws[64][128];
    int tid = threadIdx.x;
    int p   = blockIdx.x * 256 + tid;
    int b   = p >> 16;
    int pix = p & 65535;
    const float* xb = x + (size_t)b * CIN * HW + pix;

    float acc[64];
#pragma unroll
    for (int o = 0; o < 64; ++o) acc[o] = bias[o];

    for (int half = 0; half < 2; ++half) {
        for (int i = tid; i < 64 * 128; i += 256) {
            int o = i >> 7, c = i & 127;
            ws[o][c] = w[o * CIN + half * 128 + c];
        }
        __syncthreads();
        const float* xp = xb + (size_t)(half * 128) * HW;
        for (int c = 0; c < 128; c += 4) {
            float x0 = xp[(size_t)(c + 0) * HW];
            float x1 = xp[(size_t)(c + 1) * HW];
            float x2 = xp[(size_t)(c + 2) * HW];
            float x3 = xp[(size_t)(c + 3) * HW];
#pragma unroll
            for (int o = 0; o < 64; ++o) {
                float4 w4 = *(const float4*)&ws[o][c];
                acc[o] = fmaf(w4.x, x0, acc[o]);
                acc[o] = fmaf(w4.y, x1, acc[o]);
                acc[o] = fmaf(w4.z, x2, acc[o]);
                acc[o] = fmaf(w4.w, x3, acc[o]);
            }
        }
        __syncthreads();
    }
    float* yp = g_y + (size_t)b * CMID * HW + pix;
#pragma unroll
    for (int o = 0; o < 64; ++o) yp[(size_t)o * HW] = acc[o];
}

// ---------------------------------------------------------------------------
// Fused depthwise stage: separable 5x5 gaussian -> scharr0/scharr90/laplacian
// -> raw edge + per-plane sum + global max. One block per 32x32 tile per plane.
__global__ void __launch_bounds__(256) k_edge() {
    __shared__ float ys[38][40];  // y with halo 3
    __shared__ float ts[34][40];  // vertical gaussian pass
    __shared__ float ss[34][36];  // smoothed (sm) with halo 1
    __shared__ float rs[8], rm[8];

    int tid   = threadIdx.x;
    int plane = blockIdx.y;                 // b*64 + c
    int tile  = blockIdx.x;                 // 0..63
    int ty0 = (tile >> 3) * 32;
    int tx0 = (tile & 7) * 32;
    const float* yp = g_y + (size_t)plane * HW;

    // load y tile + halo (zero pad)
    for (int i = tid; i < 38 * 38; i += 256) {
        int r = i / 38, c = i - r * 38;
        int gy = ty0 - 3 + r, gx = tx0 - 3 + c;
        float v = 0.f;
        if ((unsigned)gy < 256u && (unsigned)gx < 256u) v = yp[gy * 256 + gx];
        ys[r][c] = v;
    }
    __syncthreads();

    float g1 = expf(-0.125f), g2 = expf(-0.5f);
    float sg = 1.f + 2.f * g1 + 2.f * g2;
    float invS = 1.f / (sg * sg);

    // vertical gaussian
    for (int i = tid; i < 34 * 38; i += 256) {
        int r = i / 38, c = i - r * 38;
        ts[r][c] = g2 * (ys[r][c] + ys[r + 4][c]) +
                   g1 * (ys[r + 1][c] + ys[r + 3][c]) + ys[r + 2][c];
    }
    __syncthreads();

    // horizontal gaussian; zero sm outside image (second conv's zero padding)
    for (int i = tid; i < 34 * 34; i += 256) {
        int r = i / 34, c = i - r * 34;
        float v = g2 * (ts[r][c] + ts[r][c + 4]) +
                  g1 * (ts[r][c + 1] + ts[r][c + 3]) + ts[r][c + 2];
        v *= invS;
        int gy = ty0 - 1 + r, gx = tx0 - 1 + c;
        if ((unsigned)gy >= 256u || (unsigned)gx >= 256u) v = 0.f;
        ss[r][c] = v;
    }
    __syncthreads();

    int col = tid & 31;
    int rb  = tid >> 5;
    float lsum = 0.f, lmax = 0.f;
    float* ep = g_edge + (size_t)plane * HW;
#pragma unroll
    for (int q = 0; q < 4; ++q) {
        int r = rb + q * 8;
        float a  = ss[r][col],     bb = ss[r][col + 1],     cv = ss[r][col + 2];
        float d  = ss[r + 1][col], e  = ss[r + 1][col + 1], f  = ss[r + 1][col + 2];
        float g  = ss[r + 2][col], h  = ss[r + 2][col + 1], ii = ss[r + 2][col + 2];
        float g0  = 3.f * (a - cv) + 10.f * (d - f) + 3.f * (g - ii);
        float g90 = 3.f * (a - g)  + 10.f * (bb - h) + 3.f * (cv - ii);
        float lap = 4.f * e - bb - d - f - h;
        float edge = fmaxf(fabsf(g0), fabsf(g90)) + 0.1f * fabsf(lap);
        ep[(ty0 + r) * 256 + tx0 + col] = edge;
        lsum += edge;
        lmax = fmaxf(lmax, edge);
    }

    // block reduction -> atomics
#pragma unroll
    for (int off = 16; off; off >>= 1) {
        lsum += __shfl_down_sync(0xffffffffu, lsum, off);
        lmax = fmaxf(lmax, __shfl_down_sync(0xffffffffu, lmax, off));
    }
    int wid = tid >> 5, lane = tid & 31;
    if (lane == 0) { rs[wid] = lsum; rm[wid] = lmax; }
    __syncthreads();
    if (tid == 0) {
        float s = 0.f, m = 0.f;
#pragma unroll
        for (int w2 = 0; w2 < 8; ++w2) { s += rs[w2]; m = fmaxf(m, rm[w2]); }
        atomicAdd(&g_sums[plane], s);
        atomicMax(&g_maxbits, __float_as_uint(m));
    }
}

// ---------------------------------------------------------------------------
// SE head + weight folding. Single block, 256 threads = (b, c) pairs.
// Note: clip(edge/(max+eps),0,1) is identity (edge>=0, ratio<1), so
// pooled = (raw_sum/HW) * inv, and w_eff = w_out * sigmoid(...) * inv.
__global__ void k_se(const float* __restrict__ w_fc1, const float* __restrict__ b_fc1,
                     const float* __restrict__ w_fc2, const float* __restrict__ b_fc2,
                     const float* __restrict__ w_out) {
    __shared__ float pooled[4][64];
    int tid = threadIdx.x;
    int b = tid >> 6, c = tid & 63;
    float maxv = __uint_as_float(g_maxbits);
    float inv = 1.f / (maxv + 1e-8f);
    pooled[b][c] = g_sums[tid] * (1.f / 65536.f) * inv;
    __syncthreads();

    float h[4];
#pragma unroll
    for (int j = 0; j < 4; ++j) {
        float s = b_fc1[j];
        for (int cc = 0; cc < 64; ++cc) s = fmaf(w_fc1[j * 64 + cc], pooled[b][cc], s);
        h[j] = fmaxf(s, 0.f);
    }
    float sc = b_fc2[c];
#pragma unroll
    for (int j = 0; j < 4; ++j) sc = fmaf(w_fc2[c * 4 + j], h[j], sc);
    sc = 1.f / (1.f + expf(-sc));
    float fmul = sc * inv;
    for (int o = 0; o < 64; ++o)
        g_weff[(b * 64 + o) * 64 + c] = w_out[o * 64 + c] * fmul;
}

// ---------------------------------------------------------------------------
// conv1x1 out with folded weights: out[b,o,p] = b_out[o] + sum_c weff[b,o,c]*edge[b,c,p]
__global__ void __launch_bounds__(256) k_conv_out(const float* __restrict__ bias,
                                                  float* __restrict__ out) {
    __shared__ float ws[64][64];
    int tid = threadIdx.x;
    int p   = blockIdx.x * 256 + tid;
    int b   = p >> 16;
    int pix = p & 65535;

    for (int i = tid; i < 64 * 64; i += 256) ws[i >> 6][i & 63] = g_weff[b * 4096 + i];
    __syncthreads();

    float acc[64];
#pragma unroll
    for (int o = 0; o < 64; ++o) acc[o] = bias[o];

    const float* ep = g_edge + (size_t)b * CMID * HW + pix;
    for (int c = 0; c < 64; c += 4) {
        float e0 = ep[(size_t)(c + 0) * HW];
        float e1 = ep[(size_t)(c + 1) * HW];
        float e2 = ep[(size_t)(c + 2) * HW];
        float e3 = ep[(size_t)(c + 3) * HW];
#pragma unroll
        for (int o = 0; o < 64; ++o) {
            float4 w4 = *(const float4*)&ws[o][c];
            acc[o] = fmaf(w4.x, e0, acc[o]);
            acc[o] = fmaf(w4.y, e1, acc[o]);
            acc[o] = fmaf(w4.z, e2, acc[o]);
            acc[o] = fmaf(w4.w, e3, acc[o]);
        }
    }
    float* op = out + (size_t)b * CMID * HW + pix;
#pragma unroll
    for (int o = 0; o < 64; ++o) op[(size_t)o * HW] = acc[o];
}

// ---------------------------------------------------------------------------
extern "C" void kernel_launch(void* const* d_in, const int* in_sizes, int n_in,
                              void* d_out, int out_size) {
    const float* x     = (const float*)d_in[0];
    const float* w_in  = (const float*)d_in[1];
    const float* b_in  = (const float*)d_in[2];
    const float* w_fc1 = (const float*)d_in[3];
    const float* b_fc1 = (const float*)d_in[4];
    const float* w_fc2 = (const float*)d_in[5];
    const float* b_fc2 = (const float*)d_in[6];
    const float* w_out = (const float*)d_in[7];
    const float* b_out = (const float*)d_in[8];
    float* out = (float*)d_out;

    k_init<<<1, 256>>>();
    k_conv_in<<<1024, 256>>>(x, w_in, b_in);
    k_edge<<<dim3(64, 256), 256>>>();
    k_se<<<1, 256>>>(w_fc1, b_fc1, w_fc2, b_fc2, w_out);
    k_conv_out<<<1024, 256>>>(b_out, out);
}